// round 1
// baseline (speedup 1.0000x reference)
#include <cuda_runtime.h>
#include <math.h>

#define NMAX 100000
#define EMAX 640000
#define ETOTMAX (EMAX + NMAX)
#define NH 8
#define NC 16
#define NHC 128
#define NG 64

// ---- scratch (static device globals; no allocation) ----
static __device__ float g_feat[NMAX * NHC];   // layer input features (relu'd output)
static __device__ float g_hbuf[NMAX * NHC];   // x @ W for current layer
static __device__ float g_agg [NMAX * NHC];   // aggregation accumulator
static __device__ float g_alpha[ETOTMAX * NH];// per-edge alpha -> exp values
static __device__ float g_asrc[NMAX * NH];
static __device__ float g_adst[NMAX * NH];
static __device__ float g_m   [NMAX * NH];
static __device__ float g_den [NMAX * NH];
static __device__ float g_loop[NMAX];         // self-loop edge attr (mean of incoming)
static __device__ float g_cnt [NMAX];
static __device__ float g_shead[NH];          // per-head dot(we_h, ae_h)
static __device__ float g_gsum[NG * NHC];
static __device__ float g_gcnt[NG];

__device__ __forceinline__ float atomicMaxFloat(float* addr, float value) {
    if (value >= 0.0f)
        return __int_as_float(atomicMax((int*)addr, __float_as_int(value)));
    else
        return __uint_as_float(atomicMin((unsigned int*)addr, __float_as_uint(value)));
}

// ---- self-loop attr prep ----
__global__ void k_zero_loop(int n) {
    int i = blockIdx.x * blockDim.x + threadIdx.x;
    if (i < n) { g_loop[i] = 0.0f; g_cnt[i] = 0.0f; }
}
__global__ void k_count(const int* __restrict__ dst, const float* __restrict__ eattr, int E) {
    int e = blockIdx.x * blockDim.x + threadIdx.x;
    if (e < E) {
        atomicAdd(&g_loop[dst[e]], eattr[e]);
        atomicAdd(&g_cnt[dst[e]], 1.0f);
    }
}
__global__ void k_fin_loop(int n) {
    int i = blockIdx.x * blockDim.x + threadIdx.x;
    if (i < n) g_loop[i] = g_loop[i] / fmaxf(g_cnt[i], 1.0f);
}

// ---- per-head edge-attr scalar: s_h = dot(we[h,:], ae[h,:]) ----
__global__ void k_shead(const float* __restrict__ we, const float* __restrict__ ae) {
    int h = threadIdx.x;
    if (h < NH) {
        float s = 0.0f;
        for (int c = 0; c < NC; c++) s += we[h * NC + c] * ae[h * NC + c];
        g_shead[h] = s;
    }
}

// ---- node transform: hbuf = x @ W, alpha_src/dst = head-wise dots ----
__global__ void k_transform(const float* __restrict__ x, int K, int fromFeat,
                            const float* __restrict__ w,
                            const float* __restrict__ a_s,
                            const float* __restrict__ a_d, int n) {
    int node = blockIdx.x;
    if (node >= n) return;
    int j = threadIdx.x;
    __shared__ float xs[NHC];
    const float* xp = fromFeat ? &g_feat[node * NHC] : &x[node * K];
    if (j < K) xs[j] = xp[j];
    __syncthreads();
    float acc = 0.0f;
#pragma unroll 4
    for (int k = 0; k < K; k++) acc += xs[k] * w[k * NHC + j];
    g_hbuf[node * NHC + j] = acc;
    float vs = acc * a_s[j];
    float vd = acc * a_d[j];
#pragma unroll
    for (int off = 8; off > 0; off >>= 1) {
        vs += __shfl_down_sync(0xffffffffu, vs, off, 16);
        vd += __shfl_down_sync(0xffffffffu, vd, off, 16);
    }
    if ((j & 15) == 0) {
        g_asrc[node * NH + (j >> 4)] = vs;
        g_adst[node * NH + (j >> 4)] = vd;
    }
}

// ---- reset per-layer accumulators ----
__global__ void k_reset(int n) {
    int i = blockIdx.x * blockDim.x + threadIdx.x;
    if (i < n * NHC) g_agg[i] = 0.0f;
    if (i < n * NH) { g_m[i] = -INFINITY; g_den[i] = 0.0f; }
}

// ---- edge alpha + segment max ----
__global__ void k_edge_alpha(const int* __restrict__ src, const int* __restrict__ dst,
                             const float* __restrict__ eattr, int E, int Etot) {
    int idx = blockIdx.x * blockDim.x + threadIdx.x;
    if (idx >= Etot * NH) return;
    int e = idx >> 3, h = idx & 7;
    int s, d; float ea;
    if (e < E) { s = src[e]; d = dst[e]; ea = eattr[e]; }
    else       { s = d = e - E; ea = g_loop[s]; }
    float a = g_asrc[s * NH + h] + g_adst[d * NH + h] + ea * g_shead[h];
    a = a > 0.0f ? a : 0.2f * a;
    g_alpha[idx] = a;
    atomicMaxFloat(&g_m[d * NH + h], a);
}

// ---- exp + segment sum ----
__global__ void k_exp_den(const int* __restrict__ dst, int E, int Etot) {
    int idx = blockIdx.x * blockDim.x + threadIdx.x;
    if (idx >= Etot * NH) return;
    int e = idx >> 3, h = idx & 7;
    int d = (e < E) ? dst[e] : (e - E);
    float ex = expf(g_alpha[idx] - g_m[d * NH + h]);
    g_alpha[idx] = ex;
    atomicAdd(&g_den[d * NH + h], ex);
}

// ---- weighted scatter aggregate: agg[dst] += h[src] * alpha ----
__global__ void k_aggregate(const int* __restrict__ src, const int* __restrict__ dst,
                            int E, int Etot) {
    int e = blockIdx.x;
    if (e >= Etot) return;
    int j = threadIdx.x;
    int s, d;
    if (e < E) { s = src[e]; d = dst[e]; }
    else       { s = d = e - E; }
    __shared__ float coef[NH];
    if (j < NH) coef[j] = g_alpha[e * NH + j] / (g_den[d * NH + j] + 1e-16f);
    __syncthreads();
    float v = g_hbuf[s * NHC + j] * coef[j >> 4];
    atomicAdd(&g_agg[d * NHC + j], v);
}

// ---- bias + relu into g_feat ----
__global__ void k_relu_bias(const float* __restrict__ b, int n) {
    int i = blockIdx.x * blockDim.x + threadIdx.x;
    if (i < n * NHC) g_feat[i] = fmaxf(g_agg[i] + b[i & (NHC - 1)], 0.0f);
}

// ---- pooling ----
__global__ void k_pool_zero() {
    int i = blockIdx.x * blockDim.x + threadIdx.x;
    if (i < NG * NHC) g_gsum[i] = 0.0f;
    if (i < NG) g_gcnt[i] = 0.0f;
}
__global__ void k_pool(const int* __restrict__ batch, int n) {
    const int CHUNK = 128;
    int n0 = blockIdx.x * CHUNK;
    int j = threadIdx.x;
    float acc = 0.0f;
    int cur = -1, cl = 0;
    for (int i = 0; i < CHUNK; i++) {
        int node = n0 + i;
        if (node >= n) break;
        int g = batch[node];
        if (g != cur) {
            if (cur >= 0) {
                atomicAdd(&g_gsum[cur * NHC + j], acc);
                if (j == 0) atomicAdd(&g_gcnt[cur], (float)cl);
            }
            cur = g; acc = 0.0f; cl = 0;
        }
        acc += g_feat[node * NHC + j];
        cl++;
    }
    if (cur >= 0) {
        atomicAdd(&g_gsum[cur * NHC + j], acc);
        if (j == 0) atomicAdd(&g_gcnt[cur], (float)cl);
    }
}

// ---- final MLP head ----
__global__ void k_mlp(const float* __restrict__ fw1, const float* __restrict__ fb1,
                      const float* __restrict__ fw2, const float* __restrict__ fb2,
                      float* __restrict__ out) {
    int g = blockIdx.x, t = threadIdx.x;  // 64 threads
    __shared__ float emb[NHC];
    __shared__ float ghs[64];
    float cnt = fmaxf(g_gcnt[g], 1.0f);
    emb[t]      = g_gsum[g * NHC + t] / cnt;
    emb[t + 64] = g_gsum[g * NHC + 64 + t] / cnt;
    __syncthreads();
    float acc = fb1[t];
#pragma unroll 8
    for (int k = 0; k < NHC; k++) acc += emb[k] * fw1[k * 64 + t];
    ghs[t] = fmaxf(acc, 0.0f);
    __syncthreads();
    if (t < 2) {
        float o = fb2[t];
        for (int k = 0; k < 64; k++) o += ghs[k] * fw2[k * 2 + t];
        out[g * 2 + t] = o;
    }
}

extern "C" void kernel_launch(void* const* d_in, const int* in_sizes, int n_in,
                              void* d_out, int out_size) {
    const float* x     = (const float*)d_in[0];
    const int*   ei    = (const int*)d_in[1];
    const float* eattr = (const float*)d_in[2];
    const int*   batch = (const int*)d_in[3];

    const float* W[3]  = {(const float*)d_in[4],  (const float*)d_in[10], (const float*)d_in[16]};
    const float* AS[3] = {(const float*)d_in[5],  (const float*)d_in[11], (const float*)d_in[17]};
    const float* AD[3] = {(const float*)d_in[6],  (const float*)d_in[12], (const float*)d_in[18]};
    const float* WE[3] = {(const float*)d_in[7],  (const float*)d_in[13], (const float*)d_in[19]};
    const float* AE[3] = {(const float*)d_in[8],  (const float*)d_in[14], (const float*)d_in[20]};
    const float* B[3]  = {(const float*)d_in[9],  (const float*)d_in[15], (const float*)d_in[21]};
    const float* fw1 = (const float*)d_in[22];
    const float* fb1 = (const float*)d_in[23];
    const float* fw2 = (const float*)d_in[24];
    const float* fb2 = (const float*)d_in[25];

    int N = in_sizes[3];
    int E = in_sizes[1] / 2;
    const int* src = ei;
    const int* dst = ei + E;

    // self-loop mean attr (shared by layers 2 & 3)
    k_zero_loop<<<(N + 255) / 256, 256>>>(N);
    k_count<<<(E + 255) / 256, 256>>>(dst, eattr, E);
    k_fin_loop<<<(N + 255) / 256, 256>>>(N);

    for (int l = 0; l < 3; l++) {
        int Etot = (l == 0) ? E : (E + N);
        int K = (l == 0) ? 4 : NHC;
        int T = Etot * NH;
        k_shead<<<1, NH>>>(WE[l], AE[l]);
        k_transform<<<N, NHC>>>(x, K, (l > 0) ? 1 : 0, W[l], AS[l], AD[l], N);
        k_reset<<<(N * NHC + 255) / 256, 256>>>(N);
        k_edge_alpha<<<(T + 255) / 256, 256>>>(src, dst, eattr, E, Etot);
        k_exp_den<<<(T + 255) / 256, 256>>>(dst, E, Etot);
        k_aggregate<<<Etot, NHC>>>(src, dst, E, Etot);
        k_relu_bias<<<(N * NHC + 255) / 256, 256>>>(B[l], N);
    }

    k_pool_zero<<<(NG * NHC + 255) / 256, 256>>>();
    k_pool<<<(N + 127) / 128, NHC>>>(batch, N);
    k_mlp<<<NG, 64>>>(fw1, fb1, fw2, fb2, (float*)d_out);
}

// round 2
// speedup vs baseline: 2.2587x; 2.2587x over previous
#include <cuda_runtime.h>
#include <math.h>

#define NMAX 100000
#define EMAX 640000
#define NH 8
#define NC 16
#define NHC 128
#define NG 64
#define SCAN_BLK 1024

// ---- scratch (static device globals; no allocation) ----
static __device__ float g_feat[NMAX * NHC];   // layer input features (relu'd output)
static __device__ float g_hbuf[NMAX * NHC];   // x @ W for current layer
static __device__ float g_asrc[NMAX * NH];
static __device__ float g_adst[NMAX * NH];
static __device__ float g_loop[NMAX];         // self-loop attr (mean of incoming)
static __device__ int   g_deg [NMAX];
static __device__ int   g_off [NMAX];
static __device__ int   g_cur [NMAX];
static __device__ int   g_bsum[256];
static __device__ int   g_csr_src[EMAX];
static __device__ float g_csr_ea [EMAX];
static __device__ float g_shead[3 * NH];      // per-layer per-head dot(we_h, ae_h)
static __device__ float g_gsum[NG * NHC];
static __device__ float g_gcnt[NG];

// ================= CSR build =================
__global__ void k_zero(int n) {
    int i = blockIdx.x * blockDim.x + threadIdx.x;
    if (i < n) { g_deg[i] = 0; g_loop[i] = 0.0f; }
}
__global__ void k_hist(const int* __restrict__ dst, const float* __restrict__ eattr, int E) {
    int e = blockIdx.x * blockDim.x + threadIdx.x;
    if (e < E) {
        int d = dst[e];
        atomicAdd(&g_deg[d], 1);
        atomicAdd(&g_loop[d], eattr[e]);
    }
}
__global__ void k_scan1(int n) {
    __shared__ int sh[SCAN_BLK];
    int tid = threadIdx.x;
    int i = blockIdx.x * SCAN_BLK + tid;
    int v = (i < n) ? g_deg[i] : 0;
    sh[tid] = v;
    __syncthreads();
#pragma unroll
    for (int off = 1; off < SCAN_BLK; off <<= 1) {
        int t = (tid >= off) ? sh[tid - off] : 0;
        __syncthreads();
        sh[tid] += t;
        __syncthreads();
    }
    if (i < n) g_off[i] = sh[tid] - v;           // exclusive
    if (tid == SCAN_BLK - 1) g_bsum[blockIdx.x] = sh[tid];
}
__global__ void k_scan2(int nb) {
    if (threadIdx.x == 0) {
        int run = 0;
        for (int b = 0; b < nb; b++) { int t = g_bsum[b]; g_bsum[b] = run; run += t; }
    }
}
__global__ void k_scan3(int n) {
    int i = blockIdx.x * blockDim.x + threadIdx.x;
    if (i < n) {
        int o = g_off[i] + g_bsum[i >> 10];
        g_off[i] = o;
        g_cur[i] = o;
        int dg = g_deg[i];
        g_loop[i] = g_loop[i] / fmaxf((float)dg, 1.0f);
    }
}
__global__ void k_scatter(const int* __restrict__ src, const int* __restrict__ dst,
                          const float* __restrict__ eattr, int E) {
    int e = blockIdx.x * blockDim.x + threadIdx.x;
    if (e < E) {
        int d = dst[e];
        int p = atomicAdd(&g_cur[d], 1);
        g_csr_src[p] = src[e];
        g_csr_ea[p]  = eattr[e];
    }
}

// ---- per-layer per-head edge-attr scalar: s_h = dot(we[h,:], ae[h,:]) ----
__global__ void k_shead3(const float* __restrict__ we0, const float* __restrict__ ae0,
                         const float* __restrict__ we1, const float* __restrict__ ae1,
                         const float* __restrict__ we2, const float* __restrict__ ae2) {
    int t = threadIdx.x;              // 24 threads: layer = t/8, head = t%8
    if (t >= 24) return;
    int l = t >> 3, h = t & 7;
    const float* we = (l == 0) ? we0 : (l == 1) ? we1 : we2;
    const float* ae = (l == 0) ? ae0 : (l == 1) ? ae1 : ae2;
    float s = 0.0f;
    for (int c = 0; c < NC; c++) s += we[h * NC + c] * ae[h * NC + c];
    g_shead[t] = s;
}

// ---- node transform: hbuf = x @ W, alpha_src/dst ----
__global__ void k_transform(const float* __restrict__ x, int K, int fromFeat,
                            const float* __restrict__ w,
                            const float* __restrict__ a_s,
                            const float* __restrict__ a_d, int n) {
    int node = blockIdx.x;
    if (node >= n) return;
    int j = threadIdx.x;
    __shared__ float xs[NHC];
    const float* xp = fromFeat ? &g_feat[node * NHC] : &x[node * K];
    if (j < K) xs[j] = xp[j];
    __syncthreads();
    float acc = 0.0f;
#pragma unroll 8
    for (int k = 0; k < K; k++) acc += xs[k] * w[k * NHC + j];
    g_hbuf[node * NHC + j] = acc;
    float vs = acc * a_s[j];
    float vd = acc * a_d[j];
#pragma unroll
    for (int off = 8; off > 0; off >>= 1) {
        vs += __shfl_down_sync(0xffffffffu, vs, off, 16);
        vd += __shfl_down_sync(0xffffffffu, vd, off, 16);
    }
    if ((j & 15) == 0) {
        g_asrc[node * NH + (j >> 4)] = vs;
        g_adst[node * NH + (j >> 4)] = vd;
    }
}

// ---- fused GAT dst pass: softmax + aggregate + bias + relu, one warp per node ----
__global__ void k_gat(const float* __restrict__ b, int layer, int withLoop, int n) {
    int warp = (blockIdx.x * blockDim.x + threadIdx.x) >> 5;
    int lane = threadIdx.x & 31;
    if (warp >= n) return;
    const int d = warp;
    const int h = lane >> 2;                 // head of this lane's 4 channels

    float adst_h = 0.0f, shead_h = 0.0f;
    if (lane < NH) {
        adst_h  = g_adst[d * NH + lane];
        shead_h = g_shead[layer * NH + lane];
    }

    float4 acc = make_float4(0.f, 0.f, 0.f, 0.f);
    float den_h = 0.0f;

    // self loop (layers 2,3)
    if (withLoop) {
        float w_h = 0.0f;
        if (lane < NH) {
            float a = g_asrc[d * NH + lane] + adst_h + g_loop[d] * shead_h;
            a = a > 0.0f ? a : 0.2f * a;
            w_h = expf(a);
            den_h += w_h;
        }
        float wv = __shfl_sync(0xffffffffu, w_h, h);
        float4 hv = *(const float4*)&g_hbuf[d * NHC + lane * 4];
        acc.x += wv * hv.x; acc.y += wv * hv.y; acc.z += wv * hv.z; acc.w += wv * hv.w;
    }

    int rs  = g_off[d];
    int deg = g_deg[d];
    for (int base = 0; base < deg; base += 32) {
        int s_l = 0; float ea_l = 0.0f;
        if (base + lane < deg) {
            s_l  = g_csr_src[rs + base + lane];
            ea_l = g_csr_ea [rs + base + lane];
        }
        int cnt = min(32, deg - base);
        for (int i = 0; i < cnt; i++) {
            int   s  = __shfl_sync(0xffffffffu, s_l, i);
            float ea = __shfl_sync(0xffffffffu, ea_l, i);
            float w_h = 0.0f;
            if (lane < NH) {
                float a = g_asrc[s * NH + lane] + adst_h + ea * shead_h;
                a = a > 0.0f ? a : 0.2f * a;
                w_h = expf(a);
                den_h += w_h;
            }
            float wv = __shfl_sync(0xffffffffu, w_h, h);
            float4 hv = *(const float4*)&g_hbuf[s * NHC + lane * 4];
            acc.x += wv * hv.x; acc.y += wv * hv.y; acc.z += wv * hv.z; acc.w += wv * hv.w;
        }
    }

    float den = __shfl_sync(0xffffffffu, den_h, h) + 1e-16f;
    float inv = 1.0f / den;
    float4 bv = *(const float4*)&b[lane * 4];
    float4 o;
    o.x = fmaxf(acc.x * inv + bv.x, 0.0f);
    o.y = fmaxf(acc.y * inv + bv.y, 0.0f);
    o.z = fmaxf(acc.z * inv + bv.z, 0.0f);
    o.w = fmaxf(acc.w * inv + bv.w, 0.0f);
    *(float4*)&g_feat[d * NHC + lane * 4] = o;
}

// ---- pooling ----
__global__ void k_pool_zero() {
    int i = blockIdx.x * blockDim.x + threadIdx.x;
    if (i < NG * NHC) g_gsum[i] = 0.0f;
    if (i < NG) g_gcnt[i] = 0.0f;
}
__global__ void k_pool(const int* __restrict__ batch, int n) {
    const int CHUNK = 128;
    int n0 = blockIdx.x * CHUNK;
    int j = threadIdx.x;
    float acc = 0.0f;
    int cur = -1, cl = 0;
    for (int i = 0; i < CHUNK; i++) {
        int node = n0 + i;
        if (node >= n) break;
        int g = batch[node];
        if (g != cur) {
            if (cur >= 0) {
                atomicAdd(&g_gsum[cur * NHC + j], acc);
                if (j == 0) atomicAdd(&g_gcnt[cur], (float)cl);
            }
            cur = g; acc = 0.0f; cl = 0;
        }
        acc += g_feat[node * NHC + j];
        cl++;
    }
    if (cur >= 0) {
        atomicAdd(&g_gsum[cur * NHC + j], acc);
        if (j == 0) atomicAdd(&g_gcnt[cur], (float)cl);
    }
}

// ---- final MLP head ----
__global__ void k_mlp(const float* __restrict__ fw1, const float* __restrict__ fb1,
                      const float* __restrict__ fw2, const float* __restrict__ fb2,
                      float* __restrict__ out) {
    int g = blockIdx.x, t = threadIdx.x;  // 64 threads
    __shared__ float emb[NHC];
    __shared__ float ghs[64];
    float cnt = fmaxf(g_gcnt[g], 1.0f);
    emb[t]      = g_gsum[g * NHC + t] / cnt;
    emb[t + 64] = g_gsum[g * NHC + 64 + t] / cnt;
    __syncthreads();
    float acc = fb1[t];
#pragma unroll 8
    for (int k = 0; k < NHC; k++) acc += emb[k] * fw1[k * 64 + t];
    ghs[t] = fmaxf(acc, 0.0f);
    __syncthreads();
    if (t < 2) {
        float o = fb2[t];
        for (int k = 0; k < 64; k++) o += ghs[k] * fw2[k * 2 + t];
        out[g * 2 + t] = o;
    }
}

extern "C" void kernel_launch(void* const* d_in, const int* in_sizes, int n_in,
                              void* d_out, int out_size) {
    const float* x     = (const float*)d_in[0];
    const int*   ei    = (const int*)d_in[1];
    const float* eattr = (const float*)d_in[2];
    const int*   batch = (const int*)d_in[3];

    const float* W[3]  = {(const float*)d_in[4],  (const float*)d_in[10], (const float*)d_in[16]};
    const float* AS[3] = {(const float*)d_in[5],  (const float*)d_in[11], (const float*)d_in[17]};
    const float* AD[3] = {(const float*)d_in[6],  (const float*)d_in[12], (const float*)d_in[18]};
    const float* WE[3] = {(const float*)d_in[7],  (const float*)d_in[13], (const float*)d_in[19]};
    const float* AE[3] = {(const float*)d_in[8],  (const float*)d_in[14], (const float*)d_in[20]};
    const float* B[3]  = {(const float*)d_in[9],  (const float*)d_in[15], (const float*)d_in[21]};
    const float* fw1 = (const float*)d_in[22];
    const float* fb1 = (const float*)d_in[23];
    const float* fw2 = (const float*)d_in[24];
    const float* fb2 = (const float*)d_in[25];

    int N = in_sizes[3];
    int E = in_sizes[1] / 2;
    const int* src = ei;
    const int* dst = ei + E;

    // ---- CSR build (dst-sorted) + self-loop mean attrs ----
    int nb = (N + SCAN_BLK - 1) / SCAN_BLK;
    k_zero<<<(N + 255) / 256, 256>>>(N);
    k_hist<<<(E + 255) / 256, 256>>>(dst, eattr, E);
    k_scan1<<<nb, SCAN_BLK>>>(N);
    k_scan2<<<1, 32>>>(nb);
    k_scan3<<<(N + 255) / 256, 256>>>(N);
    k_scatter<<<(E + 255) / 256, 256>>>(src, dst, eattr, E);
    k_shead3<<<1, 32>>>(WE[0], AE[0], WE[1], AE[1], WE[2], AE[2]);

    // ---- 3 GAT layers ----
    int gatBlocks = (N * 32 + 255) / 256;
    for (int l = 0; l < 3; l++) {
        int K = (l == 0) ? 4 : NHC;
        k_transform<<<N, NHC>>>(x, K, (l > 0) ? 1 : 0, W[l], AS[l], AD[l], N);
        k_gat<<<gatBlocks, 256>>>(B[l], l, (l > 0) ? 1 : 0, N);
    }

    // ---- pool + MLP head ----
    k_pool_zero<<<(NG * NHC + 255) / 256, 256>>>();
    k_pool<<<(N + 127) / 128, NHC>>>(batch, N);
    k_mlp<<<NG, 64>>>(fw1, fb1, fw2, fb2, (float*)d_out);
}

// round 3
// speedup vs baseline: 3.4889x; 1.5447x over previous
#include <cuda_runtime.h>
#include <math.h>

#define NMAX 100000
#define EMAX 640000
#define NH 8
#define NC 16
#define NHC 128
#define NG 64
#define SCAN_BLK 1024

// ---- scratch (static device globals; no allocation) ----
static __device__ float g_feat[NMAX * NHC];
static __device__ float g_hbuf[NMAX * NHC];
static __device__ float g_asrc[NMAX * NH];
static __device__ float g_adst[NMAX * NH];
static __device__ float g_loop[NMAX];
static __device__ int   g_deg [NMAX];
static __device__ int   g_off [NMAX];
static __device__ int   g_cur [NMAX];
static __device__ int   g_bsum[128];
static __device__ int   g_csr_src[EMAX];
static __device__ float g_csr_ea [EMAX];
static __device__ float g_shead[3 * NH];
static __device__ float g_gsum[NG * NHC];
static __device__ float g_gcnt[NG];

// ================= CSR build =================
__global__ void k_zero(int n) {
    int i = blockIdx.x * blockDim.x + threadIdx.x;
    if (i < n) { g_deg[i] = 0; g_loop[i] = 0.0f; }
}
__global__ void k_hist(const int* __restrict__ dst, const float* __restrict__ eattr, int E) {
    int e = blockIdx.x * blockDim.x + threadIdx.x;
    if (e < E) {
        int d = dst[e];
        atomicAdd(&g_deg[d], 1);
        atomicAdd(&g_loop[d], eattr[e]);
    }
}
__global__ void k_scan1(int n) {
    __shared__ int sh[SCAN_BLK];
    int tid = threadIdx.x;
    int i = blockIdx.x * SCAN_BLK + tid;
    int v = (i < n) ? g_deg[i] : 0;
    sh[tid] = v;
    __syncthreads();
#pragma unroll
    for (int off = 1; off < SCAN_BLK; off <<= 1) {
        int t = (tid >= off) ? sh[tid - off] : 0;
        __syncthreads();
        sh[tid] += t;
        __syncthreads();
    }
    if (i < n) g_off[i] = sh[tid] - v;           // exclusive
    if (tid == SCAN_BLK - 1) g_bsum[blockIdx.x] = sh[tid];
}
__global__ void k_scan2(int nb) {
    __shared__ int sh[128];
    int t = threadIdx.x;
    int v = (t < nb) ? g_bsum[t] : 0;
    sh[t] = v;
    __syncthreads();
#pragma unroll
    for (int off = 1; off < 128; off <<= 1) {
        int u = (t >= off) ? sh[t - off] : 0;
        __syncthreads();
        sh[t] += u;
        __syncthreads();
    }
    if (t < nb) g_bsum[t] = sh[t] - v;           // exclusive block sums
}
__global__ void k_scan3(int n) {
    int i = blockIdx.x * blockDim.x + threadIdx.x;
    if (i < n) {
        int o = g_off[i] + g_bsum[i >> 10];
        g_off[i] = o;
        g_cur[i] = o;
        g_loop[i] = g_loop[i] / fmaxf((float)g_deg[i], 1.0f);
    }
}
__global__ void k_scatter(const int* __restrict__ src, const int* __restrict__ dst,
                          const float* __restrict__ eattr, int E) {
    int e = blockIdx.x * blockDim.x + threadIdx.x;
    if (e < E) {
        int d = dst[e];
        int p = atomicAdd(&g_cur[d], 1);
        g_csr_src[p] = src[e];
        g_csr_ea[p]  = eattr[e];
    }
}

// ---- per-layer per-head edge-attr scalar ----
__global__ void k_shead3(const float* __restrict__ we0, const float* __restrict__ ae0,
                         const float* __restrict__ we1, const float* __restrict__ ae1,
                         const float* __restrict__ we2, const float* __restrict__ ae2) {
    int t = threadIdx.x;
    if (t >= 24) return;
    int l = t >> 3, h = t & 7;
    const float* we = (l == 0) ? we0 : (l == 1) ? we1 : we2;
    const float* ae = (l == 0) ? ae0 : (l == 1) ? ae1 : ae2;
    float s = 0.0f;
    for (int c = 0; c < NC; c++) s += we[h * NC + c] * ae[h * NC + c];
    g_shead[t] = s;
}

// ---- layer-0 transform: K=4, warp per node ----
__global__ void k_transform0(const float* __restrict__ x,
                             const float* __restrict__ w,
                             const float* __restrict__ a_s,
                             const float* __restrict__ a_d, int n) {
    int gid = blockIdx.x * blockDim.x + threadIdx.x;
    int node = gid >> 5;
    if (node >= n) return;
    int c = gid & 31;                        // cols 4c..4c+3
    float4 xv = *(const float4*)&x[node * 4];
    float4 w0 = *(const float4*)&w[0 * NHC + c * 4];
    float4 w1 = *(const float4*)&w[1 * NHC + c * 4];
    float4 w2 = *(const float4*)&w[2 * NHC + c * 4];
    float4 w3 = *(const float4*)&w[3 * NHC + c * 4];
    float4 acc;
    acc.x = xv.x * w0.x + xv.y * w1.x + xv.z * w2.x + xv.w * w3.x;
    acc.y = xv.x * w0.y + xv.y * w1.y + xv.z * w2.y + xv.w * w3.y;
    acc.z = xv.x * w0.z + xv.y * w1.z + xv.z * w2.z + xv.w * w3.z;
    acc.w = xv.x * w0.w + xv.y * w1.w + xv.z * w2.w + xv.w * w3.w;
    *(float4*)&g_hbuf[node * NHC + c * 4] = acc;
    float4 asv = *(const float4*)&a_s[c * 4];
    float4 adv = *(const float4*)&a_d[c * 4];
    float vs = acc.x * asv.x + acc.y * asv.y + acc.z * asv.z + acc.w * asv.w;
    float vd = acc.x * adv.x + acc.y * adv.y + acc.z * adv.z + acc.w * adv.w;
    vs += __shfl_down_sync(0xffffffffu, vs, 2, 4);
    vs += __shfl_down_sync(0xffffffffu, vs, 1, 4);
    vd += __shfl_down_sync(0xffffffffu, vd, 2, 4);
    vd += __shfl_down_sync(0xffffffffu, vd, 1, 4);
    if ((c & 3) == 0) {
        g_asrc[node * NH + (c >> 2)] = vs;
        g_adst[node * NH + (c >> 2)] = vd;
    }
}

// ---- layers 1/2 transform: K=128 register-tiled GEMM (32 nodes/block) ----
__global__ void __launch_bounds__(256) k_transform128(
        const float* __restrict__ w,
        const float* __restrict__ a_s,
        const float* __restrict__ a_d, int n) {
    __shared__ float xs[32 * NHC];           // 16KB x-tile
    int tile = blockIdx.x * 32;
    int t = threadIdx.x;
    for (int i = t; i < 32 * NHC / 4; i += 256) {
        int nl = i >> 5;                     // local node
        int node = tile + nl;
        float4 v = make_float4(0.f, 0.f, 0.f, 0.f);
        if (node < n) v = *(const float4*)&g_feat[node * NHC + (i & 31) * 4];
        *(float4*)&xs[nl * NHC + (i & 31) * 4] = v;
    }
    __syncthreads();

    int c = t & 31;                          // col group -> cols 4c..4c+3
    int m = t >> 5;                          // node group -> local nodes 4m..4m+3
    const float* xr0 = &xs[(m * 4 + 0) * NHC];
    const float* xr1 = &xs[(m * 4 + 1) * NHC];
    const float* xr2 = &xs[(m * 4 + 2) * NHC];
    const float* xr3 = &xs[(m * 4 + 3) * NHC];
    float4 a0 = {0,0,0,0}, a1 = {0,0,0,0}, a2 = {0,0,0,0}, a3 = {0,0,0,0};
#pragma unroll 4
    for (int k = 0; k < NHC; k++) {
        float4 wv = *(const float4*)&w[k * NHC + c * 4];
        float x0 = xr0[k], x1 = xr1[k], x2 = xr2[k], x3 = xr3[k];
        a0.x += x0 * wv.x; a0.y += x0 * wv.y; a0.z += x0 * wv.z; a0.w += x0 * wv.w;
        a1.x += x1 * wv.x; a1.y += x1 * wv.y; a1.z += x1 * wv.z; a1.w += x1 * wv.w;
        a2.x += x2 * wv.x; a2.y += x2 * wv.y; a2.z += x2 * wv.z; a2.w += x2 * wv.w;
        a3.x += x3 * wv.x; a3.y += x3 * wv.y; a3.z += x3 * wv.z; a3.w += x3 * wv.w;
    }
    // alpha partials: head = c>>2, reduce across the 4 lanes sharing a head
    float4 asv = *(const float4*)&a_s[c * 4];
    float4 adv = *(const float4*)&a_d[c * 4];
    float vs0 = a0.x*asv.x + a0.y*asv.y + a0.z*asv.z + a0.w*asv.w;
    float vs1 = a1.x*asv.x + a1.y*asv.y + a1.z*asv.z + a1.w*asv.w;
    float vs2 = a2.x*asv.x + a2.y*asv.y + a2.z*asv.z + a2.w*asv.w;
    float vs3 = a3.x*asv.x + a3.y*asv.y + a3.z*asv.z + a3.w*asv.w;
    float vd0 = a0.x*adv.x + a0.y*adv.y + a0.z*adv.z + a0.w*adv.w;
    float vd1 = a1.x*adv.x + a1.y*adv.y + a1.z*adv.z + a1.w*adv.w;
    float vd2 = a2.x*adv.x + a2.y*adv.y + a2.z*adv.z + a2.w*adv.w;
    float vd3 = a3.x*adv.x + a3.y*adv.y + a3.z*adv.z + a3.w*adv.w;
#pragma unroll
    for (int off = 2; off > 0; off >>= 1) {
        vs0 += __shfl_down_sync(0xffffffffu, vs0, off, 4);
        vs1 += __shfl_down_sync(0xffffffffu, vs1, off, 4);
        vs2 += __shfl_down_sync(0xffffffffu, vs2, off, 4);
        vs3 += __shfl_down_sync(0xffffffffu, vs3, off, 4);
        vd0 += __shfl_down_sync(0xffffffffu, vd0, off, 4);
        vd1 += __shfl_down_sync(0xffffffffu, vd1, off, 4);
        vd2 += __shfl_down_sync(0xffffffffu, vd2, off, 4);
        vd3 += __shfl_down_sync(0xffffffffu, vd3, off, 4);
    }
    int node0 = tile + m * 4;
    int h = c >> 2;
    if ((c & 3) == 0) {
        if (node0 + 0 < n) { g_asrc[(node0+0)*NH+h] = vs0; g_adst[(node0+0)*NH+h] = vd0; }
        if (node0 + 1 < n) { g_asrc[(node0+1)*NH+h] = vs1; g_adst[(node0+1)*NH+h] = vd1; }
        if (node0 + 2 < n) { g_asrc[(node0+2)*NH+h] = vs2; g_adst[(node0+2)*NH+h] = vd2; }
        if (node0 + 3 < n) { g_asrc[(node0+3)*NH+h] = vs3; g_adst[(node0+3)*NH+h] = vd3; }
    }
    if (node0 + 0 < n) *(float4*)&g_hbuf[(node0+0)*NHC + c*4] = a0;
    if (node0 + 1 < n) *(float4*)&g_hbuf[(node0+1)*NHC + c*4] = a1;
    if (node0 + 2 < n) *(float4*)&g_hbuf[(node0+2)*NHC + c*4] = a2;
    if (node0 + 3 < n) *(float4*)&g_hbuf[(node0+3)*NHC + c*4] = a3;
}

// ---- fused GAT dst pass: softmax + aggregate + bias + relu, one warp per node ----
__global__ void k_gat(const float* __restrict__ b, int layer, int withLoop, int n) {
    int warp = (blockIdx.x * blockDim.x + threadIdx.x) >> 5;
    int lane = threadIdx.x & 31;
    if (warp >= n) return;
    const int d = warp;
    const int h = lane >> 2;

    float adst_h = 0.0f, shead_h = 0.0f;
    if (lane < NH) {
        adst_h  = g_adst[d * NH + lane];
        shead_h = g_shead[layer * NH + lane];
    }

    float4 acc = make_float4(0.f, 0.f, 0.f, 0.f);
    float den_h = 0.0f;

    if (withLoop) {
        float w_h = 0.0f;
        if (lane < NH) {
            float a = g_asrc[d * NH + lane] + adst_h + g_loop[d] * shead_h;
            a = a > 0.0f ? a : 0.2f * a;
            w_h = expf(a);
            den_h += w_h;
        }
        float wv = __shfl_sync(0xffffffffu, w_h, h);
        float4 hv = *(const float4*)&g_hbuf[d * NHC + lane * 4];
        acc.x += wv * hv.x; acc.y += wv * hv.y; acc.z += wv * hv.z; acc.w += wv * hv.w;
    }

    int rs  = g_off[d];
    int deg = g_deg[d];
    for (int base = 0; base < deg; base += 32) {
        int s_l = 0; float ea_l = 0.0f;
        if (base + lane < deg) {
            s_l  = g_csr_src[rs + base + lane];
            ea_l = g_csr_ea [rs + base + lane];
        }
        int cnt = min(32, deg - base);
        for (int i = 0; i < cnt; i++) {
            int   s  = __shfl_sync(0xffffffffu, s_l, i);
            float ea = __shfl_sync(0xffffffffu, ea_l, i);
            float w_h = 0.0f;
            if (lane < NH) {
                float a = g_asrc[s * NH + lane] + adst_h + ea * shead_h;
                a = a > 0.0f ? a : 0.2f * a;
                w_h = expf(a);
                den_h += w_h;
            }
            float wv = __shfl_sync(0xffffffffu, w_h, h);
            float4 hv = *(const float4*)&g_hbuf[s * NHC + lane * 4];
            acc.x += wv * hv.x; acc.y += wv * hv.y; acc.z += wv * hv.z; acc.w += wv * hv.w;
        }
    }

    float den = __shfl_sync(0xffffffffu, den_h, h) + 1e-16f;
    float inv = 1.0f / den;
    float4 bv = *(const float4*)&b[lane * 4];
    float4 o;
    o.x = fmaxf(acc.x * inv + bv.x, 0.0f);
    o.y = fmaxf(acc.y * inv + bv.y, 0.0f);
    o.z = fmaxf(acc.z * inv + bv.z, 0.0f);
    o.w = fmaxf(acc.w * inv + bv.w, 0.0f);
    *(float4*)&g_feat[d * NHC + lane * 4] = o;
}

// ---- pooling ----
__global__ void k_pool_zero() {
    int i = blockIdx.x * blockDim.x + threadIdx.x;
    if (i < NG * NHC) g_gsum[i] = 0.0f;
    if (i < NG) g_gcnt[i] = 0.0f;
}
__global__ void k_pool(const int* __restrict__ batch, int n) {
    const int CHUNK = 128;
    int n0 = blockIdx.x * CHUNK;
    int j = threadIdx.x;
    float acc = 0.0f;
    int cur = -1, cl = 0;
    for (int i = 0; i < CHUNK; i++) {
        int node = n0 + i;
        if (node >= n) break;
        int g = batch[node];
        if (g != cur) {
            if (cur >= 0) {
                atomicAdd(&g_gsum[cur * NHC + j], acc);
                if (j == 0) atomicAdd(&g_gcnt[cur], (float)cl);
            }
            cur = g; acc = 0.0f; cl = 0;
        }
        acc += g_feat[node * NHC + j];
        cl++;
    }
    if (cur >= 0) {
        atomicAdd(&g_gsum[cur * NHC + j], acc);
        if (j == 0) atomicAdd(&g_gcnt[cur], (float)cl);
    }
}

// ---- final MLP head ----
__global__ void k_mlp(const float* __restrict__ fw1, const float* __restrict__ fb1,
                      const float* __restrict__ fw2, const float* __restrict__ fb2,
                      float* __restrict__ out) {
    int g = blockIdx.x, t = threadIdx.x;
    __shared__ float emb[NHC];
    __shared__ float ghs[64];
    float cnt = fmaxf(g_gcnt[g], 1.0f);
    emb[t]      = g_gsum[g * NHC + t] / cnt;
    emb[t + 64] = g_gsum[g * NHC + 64 + t] / cnt;
    __syncthreads();
    float acc = fb1[t];
#pragma unroll 8
    for (int k = 0; k < NHC; k++) acc += emb[k] * fw1[k * 64 + t];
    ghs[t] = fmaxf(acc, 0.0f);
    __syncthreads();
    if (t < 2) {
        float o = fb2[t];
        for (int k = 0; k < 64; k++) o += ghs[k] * fw2[k * 2 + t];
        out[g * 2 + t] = o;
    }
}

extern "C" void kernel_launch(void* const* d_in, const int* in_sizes, int n_in,
                              void* d_out, int out_size) {
    const float* x     = (const float*)d_in[0];
    const int*   ei    = (const int*)d_in[1];
    const float* eattr = (const float*)d_in[2];
    const int*   batch = (const int*)d_in[3];

    const float* W[3]  = {(const float*)d_in[4],  (const float*)d_in[10], (const float*)d_in[16]};
    const float* AS[3] = {(const float*)d_in[5],  (const float*)d_in[11], (const float*)d_in[17]};
    const float* AD[3] = {(const float*)d_in[6],  (const float*)d_in[12], (const float*)d_in[18]};
    const float* WE[3] = {(const float*)d_in[7],  (const float*)d_in[13], (const float*)d_in[19]};
    const float* AE[3] = {(const float*)d_in[8],  (const float*)d_in[14], (const float*)d_in[20]};
    const float* B[3]  = {(const float*)d_in[9],  (const float*)d_in[15], (const float*)d_in[21]};
    const float* fw1 = (const float*)d_in[22];
    const float* fb1 = (const float*)d_in[23];
    const float* fw2 = (const float*)d_in[24];
    const float* fb2 = (const float*)d_in[25];

    int N = in_sizes[3];
    int E = in_sizes[1] / 2;
    const int* src = ei;
    const int* dst = ei + E;

    // ---- CSR build (dst-sorted) + self-loop mean attrs ----
    int nb = (N + SCAN_BLK - 1) / SCAN_BLK;
    k_zero<<<(N + 255) / 256, 256>>>(N);
    k_hist<<<(E + 255) / 256, 256>>>(dst, eattr, E);
    k_scan1<<<nb, SCAN_BLK>>>(N);
    k_scan2<<<1, 128>>>(nb);
    k_scan3<<<(N + 255) / 256, 256>>>(N);
    k_scatter<<<(E + 255) / 256, 256>>>(src, dst, eattr, E);
    k_shead3<<<1, 32>>>(WE[0], AE[0], WE[1], AE[1], WE[2], AE[2]);

    // ---- 3 GAT layers ----
    int gatBlocks = (N * 32 + 255) / 256;
    int gemmBlocks = (N + 31) / 32;
    for (int l = 0; l < 3; l++) {
        if (l == 0)
            k_transform0<<<(N * 32 + 255) / 256, 256>>>(x, W[0], AS[0], AD[0], N);
        else
            k_transform128<<<gemmBlocks, 256>>>(W[l], AS[l], AD[l], N);
        k_gat<<<gatBlocks, 256>>>(B[l], l, (l > 0) ? 1 : 0, N);
    }

    // ---- pool + MLP head ----
    k_pool_zero<<<(NG * NHC + 255) / 256, 256>>>();
    k_pool<<<(N + 127) / 128, NHC>>>(batch, N);
    k_mlp<<<NG, 64>>>(fw1, fb1, fw2, fb2, (float*)d_out);
}

// round 4
// speedup vs baseline: 3.9979x; 1.1459x over previous
#include <cuda_runtime.h>
#include <math.h>

#define NMAX 100000
#define EMAX 640000
#define NH 8
#define NC 16
#define NHC 128
#define NG 64
#define SCAN_BLK 1024

typedef unsigned long long u64;

// ---- scratch (static device globals; no allocation) ----
static __device__ float g_feat[NMAX * NHC];
static __device__ float g_hbuf[NMAX * NHC];
static __device__ float g_asrc[NMAX * NH];
static __device__ float g_adst[NMAX * NH];
static __device__ float g_loop[NMAX];
static __device__ int   g_deg [NMAX];
static __device__ int   g_off [NMAX];
static __device__ int   g_cur [NMAX];
static __device__ int   g_bsum[128];
static __device__ int   g_csr_src[EMAX];
static __device__ float g_csr_ea [EMAX];
static __device__ float g_shead[3 * NH];
static __device__ float g_gsum[NG * NHC];
static __device__ float g_gcnt[NG];

// ---- packed f32x2 helpers ----
__device__ __forceinline__ u64 ffma2(u64 a, u64 b, u64 c) {
    u64 r; asm("fma.rn.f32x2 %0, %1, %2, %3;" : "=l"(r) : "l"(a), "l"(b), "l"(c)); return r;
}
__device__ __forceinline__ u64 dupf(float x) {
    u64 r; asm("mov.b64 %0, {%1, %1};" : "=l"(r) : "f"(x)); return r;
}
__device__ __forceinline__ float2 unpack2(u64 v) {
    float2 r; asm("mov.b64 {%0, %1}, %2;" : "=f"(r.x), "=f"(r.y) : "l"(v)); return r;
}

// ================= CSR build =================
__global__ void k_zero(int n) {
    int i = blockIdx.x * blockDim.x + threadIdx.x;
    if (i < n) { g_deg[i] = 0; g_loop[i] = 0.0f; }
}
__global__ void k_hist(const int* __restrict__ dst, const float* __restrict__ eattr, int E) {
    int e = blockIdx.x * blockDim.x + threadIdx.x;
    if (e < E) {
        int d = dst[e];
        atomicAdd(&g_deg[d], 1);
        atomicAdd(&g_loop[d], eattr[e]);
    }
}
__global__ void k_scan1(int n) {
    __shared__ int sh[SCAN_BLK];
    int tid = threadIdx.x;
    int i = blockIdx.x * SCAN_BLK + tid;
    int v = (i < n) ? g_deg[i] : 0;
    sh[tid] = v;
    __syncthreads();
#pragma unroll
    for (int off = 1; off < SCAN_BLK; off <<= 1) {
        int t = (tid >= off) ? sh[tid - off] : 0;
        __syncthreads();
        sh[tid] += t;
        __syncthreads();
    }
    if (i < n) g_off[i] = sh[tid] - v;           // exclusive
    if (tid == SCAN_BLK - 1) g_bsum[blockIdx.x] = sh[tid];
}
__global__ void k_scan2(int nb) {
    __shared__ int sh[128];
    int t = threadIdx.x;
    int v = (t < nb) ? g_bsum[t] : 0;
    sh[t] = v;
    __syncthreads();
#pragma unroll
    for (int off = 1; off < 128; off <<= 1) {
        int u = (t >= off) ? sh[t - off] : 0;
        __syncthreads();
        sh[t] += u;
        __syncthreads();
    }
    if (t < nb) g_bsum[t] = sh[t] - v;           // exclusive block sums
}
__global__ void k_scan3(int n) {
    int i = blockIdx.x * blockDim.x + threadIdx.x;
    if (i < n) {
        int o = g_off[i] + g_bsum[i >> 10];
        g_off[i] = o;
        g_cur[i] = o;
        g_loop[i] = g_loop[i] / fmaxf((float)g_deg[i], 1.0f);
    }
}
__global__ void k_scatter(const int* __restrict__ src, const int* __restrict__ dst,
                          const float* __restrict__ eattr, int E) {
    int e = blockIdx.x * blockDim.x + threadIdx.x;
    if (e < E) {
        int d = dst[e];
        int p = atomicAdd(&g_cur[d], 1);
        g_csr_src[p] = src[e];
        g_csr_ea[p]  = eattr[e];
    }
}

// ---- per-layer per-head edge-attr scalar ----
__global__ void k_shead3(const float* __restrict__ we0, const float* __restrict__ ae0,
                         const float* __restrict__ we1, const float* __restrict__ ae1,
                         const float* __restrict__ we2, const float* __restrict__ ae2) {
    int t = threadIdx.x;
    if (t >= 24) return;
    int l = t >> 3, h = t & 7;
    const float* we = (l == 0) ? we0 : (l == 1) ? we1 : we2;
    const float* ae = (l == 0) ? ae0 : (l == 1) ? ae1 : ae2;
    float s = 0.0f;
    for (int c = 0; c < NC; c++) s += we[h * NC + c] * ae[h * NC + c];
    g_shead[t] = s;
}

// ---- layer-0 transform: K=4, warp per node ----
__global__ void k_transform0(const float* __restrict__ x,
                             const float* __restrict__ w,
                             const float* __restrict__ a_s,
                             const float* __restrict__ a_d, int n) {
    int gid = blockIdx.x * blockDim.x + threadIdx.x;
    int node = gid >> 5;
    if (node >= n) return;
    int c = gid & 31;
    float4 xv = *(const float4*)&x[node * 4];
    float4 w0 = *(const float4*)&w[0 * NHC + c * 4];
    float4 w1 = *(const float4*)&w[1 * NHC + c * 4];
    float4 w2 = *(const float4*)&w[2 * NHC + c * 4];
    float4 w3 = *(const float4*)&w[3 * NHC + c * 4];
    float4 acc;
    acc.x = xv.x * w0.x + xv.y * w1.x + xv.z * w2.x + xv.w * w3.x;
    acc.y = xv.x * w0.y + xv.y * w1.y + xv.z * w2.y + xv.w * w3.y;
    acc.z = xv.x * w0.z + xv.y * w1.z + xv.z * w2.z + xv.w * w3.z;
    acc.w = xv.x * w0.w + xv.y * w1.w + xv.z * w2.w + xv.w * w3.w;
    *(float4*)&g_hbuf[node * NHC + c * 4] = acc;
    float4 asv = *(const float4*)&a_s[c * 4];
    float4 adv = *(const float4*)&a_d[c * 4];
    float vs = acc.x * asv.x + acc.y * asv.y + acc.z * asv.z + acc.w * asv.w;
    float vd = acc.x * adv.x + acc.y * adv.y + acc.z * adv.z + acc.w * adv.w;
    vs += __shfl_down_sync(0xffffffffu, vs, 2, 4);
    vs += __shfl_down_sync(0xffffffffu, vs, 1, 4);
    vd += __shfl_down_sync(0xffffffffu, vd, 2, 4);
    vd += __shfl_down_sync(0xffffffffu, vd, 1, 4);
    if ((c & 3) == 0) {
        g_asrc[node * NH + (c >> 2)] = vs;
        g_adst[node * NH + (c >> 2)] = vd;
    }
}

// ---- layers 1/2 transform: K=128 GEMM, FFMA2-packed (32 nodes/block) ----
__global__ void __launch_bounds__(256) k_transform128(
        const float* __restrict__ w,
        const float* __restrict__ a_s,
        const float* __restrict__ a_d, int n) {
    __shared__ float xs[32 * NHC];           // 16KB x-tile
    int tile = blockIdx.x * 32;
    int t = threadIdx.x;
    for (int i = t; i < 32 * NHC / 4; i += 256) {
        int nl = i >> 5;
        int node = tile + nl;
        float4 v = make_float4(0.f, 0.f, 0.f, 0.f);
        if (node < n) v = *(const float4*)&g_feat[node * NHC + (i & 31) * 4];
        *(float4*)&xs[nl * NHC + (i & 31) * 4] = v;
    }
    __syncthreads();

    int c = t & 31;                          // cols 4c..4c+3 (pairs: 4c/4c+1, 4c+2/4c+3)
    int m = t >> 5;                          // local nodes 4m..4m+3
    const float* xr0 = &xs[(m * 4 + 0) * NHC];
    const float* xr1 = &xs[(m * 4 + 1) * NHC];
    const float* xr2 = &xs[(m * 4 + 2) * NHC];
    const float* xr3 = &xs[(m * 4 + 3) * NHC];
    u64 acc[4][2] = {{0,0},{0,0},{0,0},{0,0}};
    const ulonglong2* wp = (const ulonglong2*)&w[c * 4];
#pragma unroll 4
    for (int k = 0; k < NHC; k++) {
        ulonglong2 wv = wp[k * (NHC / 4)];   // (w[k][4c],w[k][4c+1]) | (w[k][4c+2],w[k][4c+3])
        u64 d0 = dupf(xr0[k]);
        u64 d1 = dupf(xr1[k]);
        u64 d2 = dupf(xr2[k]);
        u64 d3 = dupf(xr3[k]);
        acc[0][0] = ffma2(d0, wv.x, acc[0][0]); acc[0][1] = ffma2(d0, wv.y, acc[0][1]);
        acc[1][0] = ffma2(d1, wv.x, acc[1][0]); acc[1][1] = ffma2(d1, wv.y, acc[1][1]);
        acc[2][0] = ffma2(d2, wv.x, acc[2][0]); acc[2][1] = ffma2(d2, wv.y, acc[2][1]);
        acc[3][0] = ffma2(d3, wv.x, acc[3][0]); acc[3][1] = ffma2(d3, wv.y, acc[3][1]);
    }
    // unpack to float4 per node
    float4 a4[4];
#pragma unroll
    for (int i = 0; i < 4; i++) {
        float2 lo = unpack2(acc[i][0]);
        float2 hi = unpack2(acc[i][1]);
        a4[i] = make_float4(lo.x, lo.y, hi.x, hi.y);
    }
    float4 asv = *(const float4*)&a_s[c * 4];
    float4 adv = *(const float4*)&a_d[c * 4];
    float vs[4], vd[4];
#pragma unroll
    for (int i = 0; i < 4; i++) {
        vs[i] = a4[i].x*asv.x + a4[i].y*asv.y + a4[i].z*asv.z + a4[i].w*asv.w;
        vd[i] = a4[i].x*adv.x + a4[i].y*adv.y + a4[i].z*adv.z + a4[i].w*adv.w;
    }
#pragma unroll
    for (int off = 2; off > 0; off >>= 1) {
#pragma unroll
        for (int i = 0; i < 4; i++) {
            vs[i] += __shfl_down_sync(0xffffffffu, vs[i], off, 4);
            vd[i] += __shfl_down_sync(0xffffffffu, vd[i], off, 4);
        }
    }
    int node0 = tile + m * 4;
    int h = c >> 2;
    if ((c & 3) == 0) {
#pragma unroll
        for (int i = 0; i < 4; i++)
            if (node0 + i < n) {
                g_asrc[(node0+i)*NH+h] = vs[i];
                g_adst[(node0+i)*NH+h] = vd[i];
            }
    }
#pragma unroll
    for (int i = 0; i < 4; i++)
        if (node0 + i < n) *(float4*)&g_hbuf[(node0+i)*NHC + c*4] = a4[i];
}

// ---- fused GAT dst pass: 4 edges/group, full-lane exp, warp per node ----
__global__ void k_gat(const float* __restrict__ b, int layer, int withLoop, int n) {
    int warp = (blockIdx.x * blockDim.x + threadIdx.x) >> 5;
    int lane = threadIdx.x & 31;
    if (warp >= n) return;
    const int d = warp;
    const int hA = lane & 7;     // alpha-phase head (lane = e_local*8 + hA)
    const int hC = lane >> 2;    // channel-phase head (cols lane*4..lane*4+3)

    float adst_h  = g_adst[d * NH + hA];
    float shead_h = g_shead[layer * NH + hA];
    float loopv = withLoop ? g_loop[d] : 0.0f;

    int rs  = g_off[d];
    int deg = g_deg[d];
    int degTot = deg + withLoop;   // self-loop as virtual last edge

    float4 acc = make_float4(0.f, 0.f, 0.f, 0.f);
    float den_l = 0.0f;

    for (int base = 0; base < degTot; base += 4) {
        int ei = base + (lane >> 3);
        int s_e = d;
        float ea_e = loopv;
        if (ei < deg) {
            s_e  = g_csr_src[rs + ei];
            ea_e = g_csr_ea [rs + ei];
        }
        float w_l = 0.0f;
        if (ei < degTot) {
            float a = g_asrc[s_e * NH + hA] + adst_h + ea_e * shead_h;
            a = a > 0.0f ? a : 0.2f * a;
            w_l = __expf(a);
            den_l += w_l;
        }
        int lim = min(4, degTot - base);
#pragma unroll
        for (int i = 0; i < 4; i++) {
            if (i >= lim) break;
            int   s  = __shfl_sync(0xffffffffu, s_e, i * 8);
            float wv = __shfl_sync(0xffffffffu, w_l, i * 8 + hC);
            float4 hv = *(const float4*)&g_hbuf[s * NHC + lane * 4];
            acc.x += wv * hv.x; acc.y += wv * hv.y; acc.z += wv * hv.z; acc.w += wv * hv.w;
        }
    }

    // reduce den across the 4 edge-groups (lanes h, 8+h, 16+h, 24+h)
    den_l += __shfl_xor_sync(0xffffffffu, den_l, 8);
    den_l += __shfl_xor_sync(0xffffffffu, den_l, 16);
    float den = __shfl_sync(0xffffffffu, den_l, hC) + 1e-16f;
    float inv = 1.0f / den;
    float4 bv = *(const float4*)&b[lane * 4];
    float4 o;
    o.x = fmaxf(acc.x * inv + bv.x, 0.0f);
    o.y = fmaxf(acc.y * inv + bv.y, 0.0f);
    o.z = fmaxf(acc.z * inv + bv.z, 0.0f);
    o.w = fmaxf(acc.w * inv + bv.w, 0.0f);
    *(float4*)&g_feat[d * NHC + lane * 4] = o;
}

// ---- pooling ----
__global__ void k_pool_zero() {
    int i = blockIdx.x * blockDim.x + threadIdx.x;
    if (i < NG * NHC) g_gsum[i] = 0.0f;
    if (i < NG) g_gcnt[i] = 0.0f;
}
__global__ void k_pool(const int* __restrict__ batch, int n) {
    const int CHUNK = 128;
    int n0 = blockIdx.x * CHUNK;
    int j = threadIdx.x;
    float acc = 0.0f;
    int cur = -1, cl = 0;
    for (int i = 0; i < CHUNK; i++) {
        int node = n0 + i;
        if (node >= n) break;
        int g = batch[node];
        if (g != cur) {
            if (cur >= 0) {
                atomicAdd(&g_gsum[cur * NHC + j], acc);
                if (j == 0) atomicAdd(&g_gcnt[cur], (float)cl);
            }
            cur = g; acc = 0.0f; cl = 0;
        }
        acc += g_feat[node * NHC + j];
        cl++;
    }
    if (cur >= 0) {
        atomicAdd(&g_gsum[cur * NHC + j], acc);
        if (j == 0) atomicAdd(&g_gcnt[cur], (float)cl);
    }
}

// ---- final MLP head ----
__global__ void k_mlp(const float* __restrict__ fw1, const float* __restrict__ fb1,
                      const float* __restrict__ fw2, const float* __restrict__ fb2,
                      float* __restrict__ out) {
    int g = blockIdx.x, t = threadIdx.x;
    __shared__ float emb[NHC];
    __shared__ float ghs[64];
    float cnt = fmaxf(g_gcnt[g], 1.0f);
    emb[t]      = g_gsum[g * NHC + t] / cnt;
    emb[t + 64] = g_gsum[g * NHC + 64 + t] / cnt;
    __syncthreads();
    float acc = fb1[t];
#pragma unroll 8
    for (int k = 0; k < NHC; k++) acc += emb[k] * fw1[k * 64 + t];
    ghs[t] = fmaxf(acc, 0.0f);
    __syncthreads();
    if (t < 2) {
        float o = fb2[t];
        for (int k = 0; k < 64; k++) o += ghs[k] * fw2[k * 2 + t];
        out[g * 2 + t] = o;
    }
}

extern "C" void kernel_launch(void* const* d_in, const int* in_sizes, int n_in,
                              void* d_out, int out_size) {
    const float* x     = (const float*)d_in[0];
    const int*   ei    = (const int*)d_in[1];
    const float* eattr = (const float*)d_in[2];
    const int*   batch = (const int*)d_in[3];

    const float* W[3]  = {(const float*)d_in[4],  (const float*)d_in[10], (const float*)d_in[16]};
    const float* AS[3] = {(const float*)d_in[5],  (const float*)d_in[11], (const float*)d_in[17]};
    const float* AD[3] = {(const float*)d_in[6],  (const float*)d_in[12], (const float*)d_in[18]};
    const float* WE[3] = {(const float*)d_in[7],  (const float*)d_in[13], (const float*)d_in[19]};
    const float* AE[3] = {(const float*)d_in[8],  (const float*)d_in[14], (const float*)d_in[20]};
    const float* B[3]  = {(const float*)d_in[9],  (const float*)d_in[15], (const float*)d_in[21]};
    const float* fw1 = (const float*)d_in[22];
    const float* fb1 = (const float*)d_in[23];
    const float* fw2 = (const float*)d_in[24];
    const float* fb2 = (const float*)d_in[25];

    int N = in_sizes[3];
    int E = in_sizes[1] / 2;
    const int* src = ei;
    const int* dst = ei + E;

    // ---- CSR build (dst-sorted) + self-loop mean attrs ----
    int nb = (N + SCAN_BLK - 1) / SCAN_BLK;
    k_zero<<<(N + 255) / 256, 256>>>(N);
    k_hist<<<(E + 255) / 256, 256>>>(dst, eattr, E);
    k_scan1<<<nb, SCAN_BLK>>>(N);
    k_scan2<<<1, 128>>>(nb);
    k_scan3<<<(N + 255) / 256, 256>>>(N);
    k_scatter<<<(E + 255) / 256, 256>>>(src, dst, eattr, E);
    k_shead3<<<1, 32>>>(WE[0], AE[0], WE[1], AE[1], WE[2], AE[2]);

    // ---- 3 GAT layers ----
    int gatBlocks = (N * 32 + 255) / 256;
    int gemmBlocks = (N + 31) / 32;
    for (int l = 0; l < 3; l++) {
        if (l == 0)
            k_transform0<<<(N * 32 + 255) / 256, 256>>>(x, W[0], AS[0], AD[0], N);
        else
            k_transform128<<<gemmBlocks, 256>>>(W[l], AS[l], AD[l], N);
        k_gat<<<gatBlocks, 256>>>(B[l], l, (l > 0) ? 1 : 0, N);
    }

    // ---- pool + MLP head ----
    k_pool_zero<<<(NG * NHC + 255) / 256, 256>>>();
    k_pool<<<(N + 127) / 128, NHC>>>(batch, N);
    k_mlp<<<NG, 64>>>(fw1, fb1, fw2, fb2, (float*)d_out);
}

// round 5
// speedup vs baseline: 4.6094x; 1.1530x over previous
#include <cuda_runtime.h>
#include <math.h>

#define NMAX 100000
#define EMAX 640000
#define NH 8
#define NC 16
#define NHC 128
#define NG 64
#define SLOTS 64

typedef unsigned long long u64;

// ---- scratch (static device globals; no allocation) ----
static __device__ float g_feat[NMAX * NHC];
static __device__ float g_hbuf[NMAX * NHC];
static __device__ float g_asrc[NMAX * NH];
static __device__ float g_adst[NMAX * NH];
static __device__ float g_loop[NMAX];
static __device__ int   g_deg [NMAX];
static __device__ int   g_bsrc[NMAX * SLOTS];
static __device__ float g_bea [NMAX * SLOTS];
static __device__ float g_shead[3 * NH];
static __device__ float g_gsum[NG * NHC];
static __device__ float g_gcnt[NG];

// ---- packed f32x2 helpers ----
__device__ __forceinline__ u64 ffma2(u64 a, u64 b, u64 c) {
    u64 r; asm("fma.rn.f32x2 %0, %1, %2, %3;" : "=l"(r) : "l"(a), "l"(b), "l"(c)); return r;
}
__device__ __forceinline__ u64 dupf(float x) {
    u64 r; asm("mov.b64 %0, {%1, %1};" : "=l"(r) : "f"(x)); return r;
}
__device__ __forceinline__ float2 unpack2(u64 v) {
    float2 r; asm("mov.b64 {%0, %1}, %2;" : "=f"(r.x), "=f"(r.y) : "l"(v)); return r;
}

// ================= K1: fused prep (transform0 | zero | pool_zero | shead) =================
__global__ void k_prep(const float* __restrict__ x,
                       const float* __restrict__ w,
                       const float* __restrict__ a_s,
                       const float* __restrict__ a_d,
                       const float* __restrict__ we0, const float* __restrict__ ae0,
                       const float* __restrict__ we1, const float* __restrict__ ae1,
                       const float* __restrict__ we2, const float* __restrict__ ae2,
                       int n, int tb0, int zb, int pz) {
    int bid = blockIdx.x;
    if (bid < tb0) {
        // ---- transform0: K=4, warp per node ----
        int gid = bid * 256 + threadIdx.x;
        int node = gid >> 5;
        if (node >= n) return;
        int c = gid & 31;
        float4 xv = *(const float4*)&x[node * 4];
        float4 w0 = *(const float4*)&w[0 * NHC + c * 4];
        float4 w1 = *(const float4*)&w[1 * NHC + c * 4];
        float4 w2 = *(const float4*)&w[2 * NHC + c * 4];
        float4 w3 = *(const float4*)&w[3 * NHC + c * 4];
        float4 acc;
        acc.x = xv.x * w0.x + xv.y * w1.x + xv.z * w2.x + xv.w * w3.x;
        acc.y = xv.x * w0.y + xv.y * w1.y + xv.z * w2.y + xv.w * w3.y;
        acc.z = xv.x * w0.z + xv.y * w1.z + xv.z * w2.z + xv.w * w3.z;
        acc.w = xv.x * w0.w + xv.y * w1.w + xv.z * w2.w + xv.w * w3.w;
        *(float4*)&g_hbuf[node * NHC + c * 4] = acc;
        float4 asv = *(const float4*)&a_s[c * 4];
        float4 adv = *(const float4*)&a_d[c * 4];
        float vs = acc.x * asv.x + acc.y * asv.y + acc.z * asv.z + acc.w * asv.w;
        float vd = acc.x * adv.x + acc.y * adv.y + acc.z * adv.z + acc.w * adv.w;
        vs += __shfl_down_sync(0xffffffffu, vs, 2, 4);
        vs += __shfl_down_sync(0xffffffffu, vs, 1, 4);
        vd += __shfl_down_sync(0xffffffffu, vd, 2, 4);
        vd += __shfl_down_sync(0xffffffffu, vd, 1, 4);
        if ((c & 3) == 0) {
            g_asrc[node * NH + (c >> 2)] = vs;
            g_adst[node * NH + (c >> 2)] = vd;
        }
    } else if (bid < tb0 + zb) {
        int i = (bid - tb0) * 256 + threadIdx.x;
        if (i < n) { g_deg[i] = 0; g_loop[i] = 0.0f; }
    } else if (bid < tb0 + zb + pz) {
        int i = (bid - tb0 - zb) * 256 + threadIdx.x;
        if (i < NG * NHC) g_gsum[i] = 0.0f;
        if (i < NG) g_gcnt[i] = 0.0f;
    } else {
        int t = threadIdx.x;
        if (t >= 24) return;
        int l = t >> 3, h = t & 7;
        const float* we = (l == 0) ? we0 : (l == 1) ? we1 : we2;
        const float* ae = (l == 0) ? ae0 : (l == 1) ? ae1 : ae2;
        float s = 0.0f;
        for (int cc = 0; cc < NC; cc++) s += we[h * NC + cc] * ae[h * NC + cc];
        g_shead[t] = s;
    }
}

// ================= K2: bucket scatter (hist + adjacency + loop-sum) =================
__global__ void k_scatter(const int* __restrict__ src, const int* __restrict__ dst,
                          const float* __restrict__ eattr, int E) {
    int e = blockIdx.x * blockDim.x + threadIdx.x;
    if (e < E) {
        int d = dst[e];
        float ea = eattr[e];
        int slot = atomicAdd(&g_deg[d], 1);
        if (slot < SLOTS) {
            g_bsrc[d * SLOTS + slot] = src[e];
            g_bea [d * SLOTS + slot] = ea;
        }
        atomicAdd(&g_loop[d], ea);
    }
}

// ================= K3: finalize self-loop mean =================
__global__ void k_finloop(int n) {
    int i = blockIdx.x * blockDim.x + threadIdx.x;
    if (i < n) g_loop[i] = g_loop[i] / fmaxf((float)g_deg[i], 1.0f);
}

// ---- layers 1/2 transform: K=128 GEMM, FFMA2, 64 nodes/block ----
__global__ void __launch_bounds__(512, 2) k_transform128(
        const float* __restrict__ w,
        const float* __restrict__ a_s,
        const float* __restrict__ a_d, int n) {
    __shared__ float xs[64 * NHC];           // 32KB x-tile
    int tile = blockIdx.x * 64;
    int t = threadIdx.x;
    for (int i = t; i < 64 * NHC / 4; i += 512) {
        int nl = i >> 5;
        int node = tile + nl;
        float4 v = make_float4(0.f, 0.f, 0.f, 0.f);
        if (node < n) v = *(const float4*)&g_feat[node * NHC + (i & 31) * 4];
        *(float4*)&xs[nl * NHC + (i & 31) * 4] = v;
    }
    __syncthreads();

    int c = t & 31;                          // cols 4c..4c+3
    int m = t >> 5;                          // local node group (0..15) -> nodes 4m..4m+3
    const float* xr0 = &xs[(m * 4 + 0) * NHC];
    const float* xr1 = &xs[(m * 4 + 1) * NHC];
    const float* xr2 = &xs[(m * 4 + 2) * NHC];
    const float* xr3 = &xs[(m * 4 + 3) * NHC];
    u64 acc[4][2] = {{0,0},{0,0},{0,0},{0,0}};
    const ulonglong2* wp = (const ulonglong2*)&w[c * 4];
#pragma unroll 4
    for (int k = 0; k < NHC; k++) {
        ulonglong2 wv = wp[k * (NHC / 4)];
        u64 d0 = dupf(xr0[k]);
        u64 d1 = dupf(xr1[k]);
        u64 d2 = dupf(xr2[k]);
        u64 d3 = dupf(xr3[k]);
        acc[0][0] = ffma2(d0, wv.x, acc[0][0]); acc[0][1] = ffma2(d0, wv.y, acc[0][1]);
        acc[1][0] = ffma2(d1, wv.x, acc[1][0]); acc[1][1] = ffma2(d1, wv.y, acc[1][1]);
        acc[2][0] = ffma2(d2, wv.x, acc[2][0]); acc[2][1] = ffma2(d2, wv.y, acc[2][1]);
        acc[3][0] = ffma2(d3, wv.x, acc[3][0]); acc[3][1] = ffma2(d3, wv.y, acc[3][1]);
    }
    float4 a4[4];
#pragma unroll
    for (int i = 0; i < 4; i++) {
        float2 lo = unpack2(acc[i][0]);
        float2 hi = unpack2(acc[i][1]);
        a4[i] = make_float4(lo.x, lo.y, hi.x, hi.y);
    }
    float4 asv = *(const float4*)&a_s[c * 4];
    float4 adv = *(const float4*)&a_d[c * 4];
    float vs[4], vd[4];
#pragma unroll
    for (int i = 0; i < 4; i++) {
        vs[i] = a4[i].x*asv.x + a4[i].y*asv.y + a4[i].z*asv.z + a4[i].w*asv.w;
        vd[i] = a4[i].x*adv.x + a4[i].y*adv.y + a4[i].z*adv.z + a4[i].w*adv.w;
    }
#pragma unroll
    for (int off = 2; off > 0; off >>= 1) {
#pragma unroll
        for (int i = 0; i < 4; i++) {
            vs[i] += __shfl_down_sync(0xffffffffu, vs[i], off, 4);
            vd[i] += __shfl_down_sync(0xffffffffu, vd[i], off, 4);
        }
    }
    int node0 = tile + m * 4;
    int h = c >> 2;
    if ((c & 3) == 0) {
#pragma unroll
        for (int i = 0; i < 4; i++)
            if (node0 + i < n) {
                g_asrc[(node0+i)*NH+h] = vs[i];
                g_adst[(node0+i)*NH+h] = vd[i];
            }
    }
#pragma unroll
    for (int i = 0; i < 4; i++)
        if (node0 + i < n) *(float4*)&g_hbuf[(node0+i)*NHC + c*4] = a4[i];
}

// ---- fused GAT dst pass: 4 edges/group, full-lane exp, warp per node ----
__global__ void k_gat(const float* __restrict__ b, int layer, int withLoop, int n) {
    int warp = (blockIdx.x * blockDim.x + threadIdx.x) >> 5;
    int lane = threadIdx.x & 31;
    if (warp >= n) return;
    const int d = warp;
    const int hA = lane & 7;     // alpha-phase head
    const int hC = lane >> 2;    // channel-phase head

    float adst_h  = g_adst[d * NH + hA];
    float shead_h = g_shead[layer * NH + hA];
    float loopv = withLoop ? g_loop[d] : 0.0f;

    int deg = min(g_deg[d], SLOTS);
    int degTot = deg + withLoop;

    float4 acc = make_float4(0.f, 0.f, 0.f, 0.f);
    float den_l = 0.0f;
    const int* bs = &g_bsrc[d * SLOTS];
    const float* be = &g_bea[d * SLOTS];

    for (int base = 0; base < degTot; base += 4) {
        int ei = base + (lane >> 3);
        int s_e = d;
        float ea_e = loopv;
        if (ei < deg) {
            s_e  = bs[ei];
            ea_e = be[ei];
        }
        float w_l = 0.0f;
        if (ei < degTot) {
            float a = g_asrc[s_e * NH + hA] + adst_h + ea_e * shead_h;
            a = a > 0.0f ? a : 0.2f * a;
            w_l = __expf(a);
            den_l += w_l;
        }
        int lim = min(4, degTot - base);
#pragma unroll
        for (int i = 0; i < 4; i++) {
            if (i >= lim) break;
            int   s  = __shfl_sync(0xffffffffu, s_e, i * 8);
            float wv = __shfl_sync(0xffffffffu, w_l, i * 8 + hC);
            float4 hv = *(const float4*)&g_hbuf[s * NHC + lane * 4];
            acc.x += wv * hv.x; acc.y += wv * hv.y; acc.z += wv * hv.z; acc.w += wv * hv.w;
        }
    }

    den_l += __shfl_xor_sync(0xffffffffu, den_l, 8);
    den_l += __shfl_xor_sync(0xffffffffu, den_l, 16);
    float den = __shfl_sync(0xffffffffu, den_l, hC) + 1e-16f;
    float inv = 1.0f / den;
    float4 bv = *(const float4*)&b[lane * 4];
    float4 o;
    o.x = fmaxf(acc.x * inv + bv.x, 0.0f);
    o.y = fmaxf(acc.y * inv + bv.y, 0.0f);
    o.z = fmaxf(acc.z * inv + bv.z, 0.0f);
    o.w = fmaxf(acc.w * inv + bv.w, 0.0f);
    *(float4*)&g_feat[d * NHC + lane * 4] = o;
}

// ---- pooling (4-deep software pipeline) ----
__global__ void k_pool(const int* __restrict__ batch, int n) {
    const int CHUNK = 128;
    int n0 = blockIdx.x * CHUNK;
    int j = threadIdx.x;
    int lim = min(CHUNK, n - n0);
    float acc = 0.0f;
    int cur = -1, cl = 0;
    for (int i0 = 0; i0 < lim; i0 += 4) {
        float f[4]; int bi[4];
        int cnt = min(4, lim - i0);
#pragma unroll
        for (int k = 0; k < 4; k++) {
            if (k < cnt) {
                f[k]  = g_feat[(u64)(n0 + i0 + k) * NHC + j];
                bi[k] = batch[n0 + i0 + k];
            }
        }
#pragma unroll
        for (int k = 0; k < 4; k++) {
            if (k >= cnt) break;
            if (bi[k] != cur) {
                if (cur >= 0) {
                    atomicAdd(&g_gsum[cur * NHC + j], acc);
                    if (j == 0) atomicAdd(&g_gcnt[cur], (float)cl);
                }
                cur = bi[k]; acc = 0.0f; cl = 0;
            }
            acc += f[k];
            cl++;
        }
    }
    if (cur >= 0) {
        atomicAdd(&g_gsum[cur * NHC + j], acc);
        if (j == 0) atomicAdd(&g_gcnt[cur], (float)cl);
    }
}

// ---- final MLP head ----
__global__ void k_mlp(const float* __restrict__ fw1, const float* __restrict__ fb1,
                      const float* __restrict__ fw2, const float* __restrict__ fb2,
                      float* __restrict__ out) {
    int g = blockIdx.x, t = threadIdx.x;
    __shared__ float emb[NHC];
    __shared__ float ghs[64];
    float cnt = fmaxf(g_gcnt[g], 1.0f);
    emb[t]      = g_gsum[g * NHC + t] / cnt;
    emb[t + 64] = g_gsum[g * NHC + 64 + t] / cnt;
    __syncthreads();
    float acc = fb1[t];
#pragma unroll 8
    for (int k = 0; k < NHC; k++) acc += emb[k] * fw1[k * 64 + t];
    ghs[t] = fmaxf(acc, 0.0f);
    __syncthreads();
    if (t < 2) {
        float o = fb2[t];
        for (int k = 0; k < 64; k++) o += ghs[k] * fw2[k * 2 + t];
        out[g * 2 + t] = o;
    }
}

extern "C" void kernel_launch(void* const* d_in, const int* in_sizes, int n_in,
                              void* d_out, int out_size) {
    const float* x     = (const float*)d_in[0];
    const int*   ei    = (const int*)d_in[1];
    const float* eattr = (const float*)d_in[2];
    const int*   batch = (const int*)d_in[3];

    const float* W[3]  = {(const float*)d_in[4],  (const float*)d_in[10], (const float*)d_in[16]};
    const float* AS[3] = {(const float*)d_in[5],  (const float*)d_in[11], (const float*)d_in[17]};
    const float* AD[3] = {(const float*)d_in[6],  (const float*)d_in[12], (const float*)d_in[18]};
    const float* WE[3] = {(const float*)d_in[7],  (const float*)d_in[13], (const float*)d_in[19]};
    const float* AE[3] = {(const float*)d_in[8],  (const float*)d_in[14], (const float*)d_in[20]};
    const float* B[3]  = {(const float*)d_in[9],  (const float*)d_in[15], (const float*)d_in[21]};
    const float* fw1 = (const float*)d_in[22];
    const float* fb1 = (const float*)d_in[23];
    const float* fw2 = (const float*)d_in[24];
    const float* fb2 = (const float*)d_in[25];

    int N = in_sizes[3];
    int E = in_sizes[1] / 2;
    const int* src = ei;
    const int* dst = ei + E;

    int tb0 = (N * 32 + 255) / 256;
    int zb  = (N + 255) / 256;
    int pz  = (NG * NHC + 255) / 256;

    // K1: transform0 + zero + pool_zero + shead   (fused, grid-split)
    k_prep<<<tb0 + zb + pz + 1, 256>>>(x, W[0], AS[0], AD[0],
                                       WE[0], AE[0], WE[1], AE[1], WE[2], AE[2],
                                       N, tb0, zb, pz);
    // K2: bucket adjacency build
    k_scatter<<<(E + 255) / 256, 256>>>(src, dst, eattr, E);
    // K3: self-loop mean
    k_finloop<<<(N + 255) / 256, 256>>>(N);

    int gatBlocks  = (N * 32 + 255) / 256;
    int gemmBlocks = (N + 63) / 64;
    // K4: gat layer 0  (ncu capture slot)
    k_gat<<<gatBlocks, 256>>>(B[0], 0, 0, N);
    for (int l = 1; l < 3; l++) {
        k_transform128<<<gemmBlocks, 512>>>(W[l], AS[l], AD[l], N);
        k_gat<<<gatBlocks, 256>>>(B[l], l, 1, N);
    }

    k_pool<<<(N + 127) / 128, NHC>>>(batch, N);
    k_mlp<<<NG, 64>>>(fw1, fb1, fw2, fb2, (float*)d_out);
}

// round 6
// speedup vs baseline: 4.7724x; 1.0354x over previous
#include <cuda_runtime.h>
#include <math.h>

#define NMAX 100000
#define EMAX 640000
#define NH 8
#define NC 16
#define NHC 128
#define NG 64
#define SLOTS 64

typedef unsigned long long u64;

// ---- scratch (static device globals; no allocation) ----
static __device__ float g_feat[NMAX * NHC];
static __device__ float g_hbuf[NMAX * NHC];
static __device__ float g_asrc[NMAX * NH];
static __device__ float g_adst[NMAX * NH];
static __device__ float g_loop[NMAX];
static __device__ int   g_deg [NMAX];
static __device__ int2  g_badj[NMAX * SLOTS];   // (src, ea bits)
static __device__ float g_shead[3 * NH];
static __device__ float g_gsum[NG * NHC];
static __device__ float g_gcnt[NG];

// ---- packed f32x2 helpers ----
__device__ __forceinline__ u64 ffma2(u64 a, u64 b, u64 c) {
    u64 r; asm("fma.rn.f32x2 %0, %1, %2, %3;" : "=l"(r) : "l"(a), "l"(b), "l"(c)); return r;
}
__device__ __forceinline__ u64 dupf(float x) {
    u64 r; asm("mov.b64 %0, {%1, %1};" : "=l"(r) : "f"(x)); return r;
}
__device__ __forceinline__ float2 unpack2(u64 v) {
    float2 r; asm("mov.b64 {%0, %1}, %2;" : "=f"(r.x), "=f"(r.y) : "l"(v)); return r;
}

// ================= K1: fused prep (transform0 | zero | pool_zero | shead) =================
__global__ void k_prep(const float* __restrict__ x,
                       const float* __restrict__ w,
                       const float* __restrict__ a_s,
                       const float* __restrict__ a_d,
                       const float* __restrict__ we0, const float* __restrict__ ae0,
                       const float* __restrict__ we1, const float* __restrict__ ae1,
                       const float* __restrict__ we2, const float* __restrict__ ae2,
                       int n, int tb0, int zb, int pz) {
    int bid = blockIdx.x;
    if (bid < tb0) {
        int gid = bid * 256 + threadIdx.x;
        int node = gid >> 5;
        if (node >= n) return;
        int c = gid & 31;
        float4 xv = *(const float4*)&x[node * 4];
        float4 w0 = *(const float4*)&w[0 * NHC + c * 4];
        float4 w1 = *(const float4*)&w[1 * NHC + c * 4];
        float4 w2 = *(const float4*)&w[2 * NHC + c * 4];
        float4 w3 = *(const float4*)&w[3 * NHC + c * 4];
        float4 acc;
        acc.x = xv.x * w0.x + xv.y * w1.x + xv.z * w2.x + xv.w * w3.x;
        acc.y = xv.x * w0.y + xv.y * w1.y + xv.z * w2.y + xv.w * w3.y;
        acc.z = xv.x * w0.z + xv.y * w1.z + xv.z * w2.z + xv.w * w3.z;
        acc.w = xv.x * w0.w + xv.y * w1.w + xv.z * w2.w + xv.w * w3.w;
        *(float4*)&g_hbuf[node * NHC + c * 4] = acc;
        float4 asv = *(const float4*)&a_s[c * 4];
        float4 adv = *(const float4*)&a_d[c * 4];
        float vs = acc.x * asv.x + acc.y * asv.y + acc.z * asv.z + acc.w * asv.w;
        float vd = acc.x * adv.x + acc.y * adv.y + acc.z * adv.z + acc.w * adv.w;
        vs += __shfl_down_sync(0xffffffffu, vs, 2, 4);
        vs += __shfl_down_sync(0xffffffffu, vs, 1, 4);
        vd += __shfl_down_sync(0xffffffffu, vd, 2, 4);
        vd += __shfl_down_sync(0xffffffffu, vd, 1, 4);
        if ((c & 3) == 0) {
            g_asrc[node * NH + (c >> 2)] = vs;
            g_adst[node * NH + (c >> 2)] = vd;
        }
    } else if (bid < tb0 + zb) {
        int i = (bid - tb0) * 256 + threadIdx.x;
        if (i < n) { g_deg[i] = 0; g_loop[i] = 0.0f; }
    } else if (bid < tb0 + zb + pz) {
        int i = (bid - tb0 - zb) * 256 + threadIdx.x;
        if (i < NG * NHC) g_gsum[i] = 0.0f;
        if (i < NG) g_gcnt[i] = 0.0f;
    } else {
        int t = threadIdx.x;
        if (t >= 24) return;
        int l = t >> 3, h = t & 7;
        const float* we = (l == 0) ? we0 : (l == 1) ? we1 : we2;
        const float* ae = (l == 0) ? ae0 : (l == 1) ? ae1 : ae2;
        float s = 0.0f;
        for (int cc = 0; cc < NC; cc++) s += we[h * NC + cc] * ae[h * NC + cc];
        g_shead[t] = s;
    }
}

// ================= K2: bucket scatter =================
__global__ void k_scatter(const int* __restrict__ src, const int* __restrict__ dst,
                          const float* __restrict__ eattr, int E) {
    int e = blockIdx.x * blockDim.x + threadIdx.x;
    if (e < E) {
        int d = dst[e];
        float ea = eattr[e];
        int slot = atomicAdd(&g_deg[d], 1);
        if (slot < SLOTS) g_badj[d * SLOTS + slot] = make_int2(src[e], __float_as_int(ea));
        atomicAdd(&g_loop[d], ea);
    }
}

// ================= K3: finalize self-loop mean =================
__global__ void k_finloop(int n) {
    int i = blockIdx.x * blockDim.x + threadIdx.x;
    if (i < n) g_loop[i] = g_loop[i] / fmaxf((float)g_deg[i], 1.0f);
}

// ---- layers 1/2 transform: K=128 GEMM, FFMA2, 64 nodes/block ----
__global__ void __launch_bounds__(512, 2) k_transform128(
        const float* __restrict__ w,
        const float* __restrict__ a_s,
        const float* __restrict__ a_d, int n) {
    __shared__ float xs[64 * NHC];           // 32KB x-tile
    int tile = blockIdx.x * 64;
    int t = threadIdx.x;
    for (int i = t; i < 64 * NHC / 4; i += 512) {
        int nl = i >> 5;
        int node = tile + nl;
        float4 v = make_float4(0.f, 0.f, 0.f, 0.f);
        if (node < n) v = *(const float4*)&g_feat[node * NHC + (i & 31) * 4];
        *(float4*)&xs[nl * NHC + (i & 31) * 4] = v;
    }
    __syncthreads();

    int c = t & 31;
    int m = t >> 5;
    const float* xr0 = &xs[(m * 4 + 0) * NHC];
    const float* xr1 = &xs[(m * 4 + 1) * NHC];
    const float* xr2 = &xs[(m * 4 + 2) * NHC];
    const float* xr3 = &xs[(m * 4 + 3) * NHC];
    u64 acc[4][2] = {{0,0},{0,0},{0,0},{0,0}};
    const ulonglong2* wp = (const ulonglong2*)&w[c * 4];
#pragma unroll 4
    for (int k = 0; k < NHC; k++) {
        ulonglong2 wv = wp[k * (NHC / 4)];
        u64 d0 = dupf(xr0[k]);
        u64 d1 = dupf(xr1[k]);
        u64 d2 = dupf(xr2[k]);
        u64 d3 = dupf(xr3[k]);
        acc[0][0] = ffma2(d0, wv.x, acc[0][0]); acc[0][1] = ffma2(d0, wv.y, acc[0][1]);
        acc[1][0] = ffma2(d1, wv.x, acc[1][0]); acc[1][1] = ffma2(d1, wv.y, acc[1][1]);
        acc[2][0] = ffma2(d2, wv.x, acc[2][0]); acc[2][1] = ffma2(d2, wv.y, acc[2][1]);
        acc[3][0] = ffma2(d3, wv.x, acc[3][0]); acc[3][1] = ffma2(d3, wv.y, acc[3][1]);
    }
    float4 a4[4];
#pragma unroll
    for (int i = 0; i < 4; i++) {
        float2 lo = unpack2(acc[i][0]);
        float2 hi = unpack2(acc[i][1]);
        a4[i] = make_float4(lo.x, lo.y, hi.x, hi.y);
    }
    float4 asv = *(const float4*)&a_s[c * 4];
    float4 adv = *(const float4*)&a_d[c * 4];
    float vs[4], vd[4];
#pragma unroll
    for (int i = 0; i < 4; i++) {
        vs[i] = a4[i].x*asv.x + a4[i].y*asv.y + a4[i].z*asv.z + a4[i].w*asv.w;
        vd[i] = a4[i].x*adv.x + a4[i].y*adv.y + a4[i].z*adv.z + a4[i].w*adv.w;
    }
#pragma unroll
    for (int off = 2; off > 0; off >>= 1) {
#pragma unroll
        for (int i = 0; i < 4; i++) {
            vs[i] += __shfl_down_sync(0xffffffffu, vs[i], off, 4);
            vd[i] += __shfl_down_sync(0xffffffffu, vd[i], off, 4);
        }
    }
    int node0 = tile + m * 4;
    int h = c >> 2;
    if ((c & 3) == 0) {
#pragma unroll
        for (int i = 0; i < 4; i++)
            if (node0 + i < n) {
                g_asrc[(node0+i)*NH+h] = vs[i];
                g_adst[(node0+i)*NH+h] = vd[i];
            }
    }
#pragma unroll
    for (int i = 0; i < 4; i++)
        if (node0 + i < n) *(float4*)&g_hbuf[(node0+i)*NHC + c*4] = a4[i];
}

// ---- fused GAT dst pass: 8 edges/iter, warp per node ----
__global__ void __launch_bounds__(256) k_gat(const float* __restrict__ b,
                                             int layer, int withLoop, int n) {
    int warp = (blockIdx.x * blockDim.x + threadIdx.x) >> 5;
    int lane = threadIdx.x & 31;
    if (warp >= n) return;
    const int d = warp;
    const int hA = lane & 7;     // alpha-phase head
    const int hC = lane >> 2;    // channel-phase head

    float adst_h  = g_adst[d * NH + hA];
    float shead_h = g_shead[layer * NH + hA];
    float loopv = withLoop ? g_loop[d] : 0.0f;

    int deg = min(g_deg[d], SLOTS);
    int degTot = deg + withLoop;   // self-loop as virtual last edge

    float4 acc = make_float4(0.f, 0.f, 0.f, 0.f);
    float den_l = 0.0f;
    const int2* ba = &g_badj[d * SLOTS];

    for (int base = 0; base < degTot; base += 8) {
        // lanes 0..7 load up to 8 edges (default = self-loop)
        int2 ed = make_int2(d, __float_as_int(loopv));
        int el = base + lane;
        if (lane < 8 && el < deg) ed = ba[el];

        // each lane computes exp-weight for 2 edge/head combos
        int k0 = lane >> 3, k1 = 4 + (lane >> 3);
        int   s0  = __shfl_sync(0xffffffffu, ed.x, k0);
        float ea0 = __int_as_float(__shfl_sync(0xffffffffu, ed.y, k0));
        int   s1  = __shfl_sync(0xffffffffu, ed.x, k1);
        float ea1 = __int_as_float(__shfl_sync(0xffffffffu, ed.y, k1));
        float w0 = 0.0f, w1 = 0.0f;
        if (base + k0 < degTot) {
            float a = g_asrc[s0 * NH + hA] + adst_h + ea0 * shead_h;
            a = a > 0.0f ? a : 0.2f * a;
            w0 = __expf(a);
            den_l += w0;
        }
        if (base + k1 < degTot) {
            float a = g_asrc[s1 * NH + hA] + adst_h + ea1 * shead_h;
            a = a > 0.0f ? a : 0.2f * a;
            w1 = __expf(a);
            den_l += w1;
        }

        int lim = min(8, degTot - base);
#pragma unroll
        for (int i = 0; i < 8; i++) {
            if (i >= lim) break;
            int s = __shfl_sync(0xffffffffu, ed.x, i);
            float wv = (i < 4)
                ? __shfl_sync(0xffffffffu, w0, (i & 3) * 8 + hC)
                : __shfl_sync(0xffffffffu, w1, (i & 3) * 8 + hC);
            float4 hv = *(const float4*)&g_hbuf[(u64)s * NHC + lane * 4];
            acc.x += wv * hv.x; acc.y += wv * hv.y; acc.z += wv * hv.z; acc.w += wv * hv.w;
        }
    }

    den_l += __shfl_xor_sync(0xffffffffu, den_l, 8);
    den_l += __shfl_xor_sync(0xffffffffu, den_l, 16);
    float den = __shfl_sync(0xffffffffu, den_l, hC) + 1e-16f;
    float inv = 1.0f / den;
    float4 bv = *(const float4*)&b[lane * 4];
    float4 o;
    o.x = fmaxf(acc.x * inv + bv.x, 0.0f);
    o.y = fmaxf(acc.y * inv + bv.y, 0.0f);
    o.z = fmaxf(acc.z * inv + bv.z, 0.0f);
    o.w = fmaxf(acc.w * inv + bv.w, 0.0f);
    *(float4*)&g_feat[d * NHC + lane * 4] = o;
}

// ---- pooling (4-deep software pipeline) ----
__global__ void k_pool(const int* __restrict__ batch, int n) {
    const int CHUNK = 128;
    int n0 = blockIdx.x * CHUNK;
    int j = threadIdx.x;
    int lim = min(CHUNK, n - n0);
    float acc = 0.0f;
    int cur = -1, cl = 0;
    for (int i0 = 0; i0 < lim; i0 += 4) {
        float f[4]; int bi[4];
        int cnt = min(4, lim - i0);
#pragma unroll
        for (int k = 0; k < 4; k++) {
            if (k < cnt) {
                f[k]  = g_feat[(u64)(n0 + i0 + k) * NHC + j];
                bi[k] = batch[n0 + i0 + k];
            }
        }
#pragma unroll
        for (int k = 0; k < 4; k++) {
            if (k >= cnt) break;
            if (bi[k] != cur) {
                if (cur >= 0) {
                    atomicAdd(&g_gsum[cur * NHC + j], acc);
                    if (j == 0) atomicAdd(&g_gcnt[cur], (float)cl);
                }
                cur = bi[k]; acc = 0.0f; cl = 0;
            }
            acc += f[k];
            cl++;
        }
    }
    if (cur >= 0) {
        atomicAdd(&g_gsum[cur * NHC + j], acc);
        if (j == 0) atomicAdd(&g_gcnt[cur], (float)cl);
    }
}

// ---- final MLP head ----
__global__ void k_mlp(const float* __restrict__ fw1, const float* __restrict__ fb1,
                      const float* __restrict__ fw2, const float* __restrict__ fb2,
                      float* __restrict__ out) {
    int g = blockIdx.x, t = threadIdx.x;
    __shared__ float emb[NHC];
    __shared__ float ghs[64];
    float cnt = fmaxf(g_gcnt[g], 1.0f);
    emb[t]      = g_gsum[g * NHC + t] / cnt;
    emb[t + 64] = g_gsum[g * NHC + 64 + t] / cnt;
    __syncthreads();
    float acc = fb1[t];
#pragma unroll 8
    for (int k = 0; k < NHC; k++) acc += emb[k] * fw1[k * 64 + t];
    ghs[t] = fmaxf(acc, 0.0f);
    __syncthreads();
    if (t < 2) {
        float o = fb2[t];
        for (int k = 0; k < 64; k++) o += ghs[k] * fw2[k * 2 + t];
        out[g * 2 + t] = o;
    }
}

extern "C" void kernel_launch(void* const* d_in, const int* in_sizes, int n_in,
                              void* d_out, int out_size) {
    const float* x     = (const float*)d_in[0];
    const int*   ei    = (const int*)d_in[1];
    const float* eattr = (const float*)d_in[2];
    const int*   batch = (const int*)d_in[3];

    const float* W[3]  = {(const float*)d_in[4],  (const float*)d_in[10], (const float*)d_in[16]};
    const float* AS[3] = {(const float*)d_in[5],  (const float*)d_in[11], (const float*)d_in[17]};
    const float* AD[3] = {(const float*)d_in[6],  (const float*)d_in[12], (const float*)d_in[18]};
    const float* WE[3] = {(const float*)d_in[7],  (const float*)d_in[13], (const float*)d_in[19]};
    const float* AE[3] = {(const float*)d_in[8],  (const float*)d_in[14], (const float*)d_in[20]};
    const float* B[3]  = {(const float*)d_in[9],  (const float*)d_in[15], (const float*)d_in[21]};
    const float* fw1 = (const float*)d_in[22];
    const float* fb1 = (const float*)d_in[23];
    const float* fw2 = (const float*)d_in[24];
    const float* fb2 = (const float*)d_in[25];

    int N = in_sizes[3];
    int E = in_sizes[1] / 2;
    const int* src = ei;
    const int* dst = ei + E;

    int tb0 = (N * 32 + 255) / 256;
    int zb  = (N + 255) / 256;
    int pz  = (NG * NHC + 255) / 256;

    k_prep<<<tb0 + zb + pz + 1, 256>>>(x, W[0], AS[0], AD[0],
                                       WE[0], AE[0], WE[1], AE[1], WE[2], AE[2],
                                       N, tb0, zb, pz);
    k_scatter<<<(E + 255) / 256, 256>>>(src, dst, eattr, E);
    k_finloop<<<(N + 255) / 256, 256>>>(N);

    int gatBlocks  = (N * 32 + 255) / 256;
    int gemmBlocks = (N + 63) / 64;
    // launch #4: gat layer 0 (ncu capture slot)
    k_gat<<<gatBlocks, 256>>>(B[0], 0, 0, N);
    for (int l = 1; l < 3; l++) {
        k_transform128<<<gemmBlocks, 512>>>(W[l], AS[l], AD[l], N);
        k_gat<<<gatBlocks, 256>>>(B[l], l, 1, N);
    }

    k_pool<<<(N + 127) / 128, NHC>>>(batch, N);
    k_mlp<<<NG, 64>>>(fw1, fb1, fw2, fb2, (float*)d_out);
}